// round 5
// baseline (speedup 1.0000x reference)
#include <cuda_runtime.h>
#include <cuda_bf16.h>
#include <cstdint>

#define B_    4
#define C_    128
#define H_    256
#define W_    256
#define GW    28
#define QB    784
#define Q_    3136
#define NPOS  29
#define NNEG  80
#define NOFF  109
#define ND    3136
#define NCOL  3217   /* 1 + 80 + 3136 */
#define MPAD  3200   /* 25 * 128 */
#define KSP   384    /* 3 * 128 : [hiA|hiA|loA] x [hiB|loB|hiB] */

static const size_t S_SCORES = (size_t)Q_ * NCOL;   // 10,088,512

// ---------------- offsets, exact reference enumeration order (j outer asc, i inner asc)
__constant__ int c_off[NOFF][2] = {
    // ---- 29 positives ----
    {0,-3},
    {-2,-2},{-1,-2},{0,-2},{1,-2},{2,-2},
    {-2,-1},{-1,-1},{0,-1},{1,-1},{2,-1},
    {-3,0},{-2,0},{-1,0},{0,0},{1,0},{2,0},{3,0},
    {-2,1},{-1,1},{0,1},{1,1},{2,1},
    {-2,2},{-1,2},{0,2},{1,2},{2,2},
    {0,3},
    // ---- 80 negatives ----
    {0,-7},
    {-3,-6},{-2,-6},{-1,-6},{0,-6},{1,-6},{2,-6},{3,-6},
    {-4,-5},{-3,-5},{-2,-5},{-1,-5},{0,-5},{1,-5},{2,-5},{3,-5},{4,-5},
    {-5,-4},{-4,-4},{-3,-4},{3,-4},{4,-4},{5,-4},
    {-6,-3},{-5,-3},{-4,-3},{4,-3},{5,-3},{6,-3},
    {-6,-2},{-5,-2},{5,-2},{6,-2},
    {-6,-1},{-5,-1},{5,-1},{6,-1},
    {-7,0},{-6,0},{-5,0},{5,0},{6,0},{7,0},
    {-6,1},{-5,1},{5,1},{6,1},
    {-6,2},{-5,2},{5,2},{6,2},
    {-6,3},{-5,3},{-4,3},{4,3},{5,3},{6,3},
    {-5,4},{-4,4},{-3,4},{3,4},{4,4},{5,4},
    {-4,5},{-3,5},{-2,5},{-1,5},{0,5},{1,5},{2,5},{3,5},{4,5},
    {-3,6},{-2,6},{-1,6},{0,6},{1,6},{2,6},{3,6},
    {0,7}
};

// ---------------- device scratch ----------------
__device__ float g_feat2t[(size_t)B_ * H_ * W_ * C_];       // feat2 -> (B,H,W,C)
__device__ __nv_bfloat16 g_a[(size_t)MPAD * KSP];           // split queries
__device__ __nv_bfloat16 g_b[(size_t)MPAD * KSP];           // split distractors
__device__ int2  g_xy2[Q_];

// ---------------- helpers ----------------
__device__ __forceinline__ void ldsm_x4(uint32_t (&r)[4], const void* p) {
    uint32_t a = (uint32_t)__cvta_generic_to_shared(p);
    asm volatile("ldmatrix.sync.aligned.m8n8.x4.shared.b16 {%0,%1,%2,%3}, [%4];"
        : "=r"(r[0]), "=r"(r[1]), "=r"(r[2]), "=r"(r[3]) : "r"(a));
}
__device__ __forceinline__ void mma_bf16(float (&d)[4], const uint32_t (&a)[4],
                                         uint32_t b0, uint32_t b1) {
    asm volatile("mma.sync.aligned.m16n8k16.row.col.f32.bf16.bf16.f32 "
        "{%0,%1,%2,%3}, {%4,%5,%6,%7}, {%8,%9}, {%0,%1,%2,%3};"
        : "+f"(d[0]), "+f"(d[1]), "+f"(d[2]), "+f"(d[3])
        : "r"(a[0]), "r"(a[1]), "r"(a[2]), "r"(a[3]), "r"(b0), "r"(b1));
}

// ---------------- transpose feat2 (B,C,H,W) -> (B,HW,C)  [R2 version: 59% DRAM]
__global__ void k_transpose(const float* __restrict__ f2) {
    __shared__ float tile[32][33];
    int b  = blockIdx.z;
    int p0 = blockIdx.x * 32;     // pixel (h*W+w)
    int c0 = blockIdx.y * 32;     // channel
    int tx = threadIdx.x, ty = threadIdx.y;     // 32 x 8
    const float* src = f2 + (size_t)b * C_ * H_ * W_;
    float* dst = g_feat2t + (size_t)b * H_ * W_ * C_;
#pragma unroll
    for (int i = 0; i < 32; i += 8)
        tile[ty + i][tx] = src[(size_t)(c0 + ty + i) * (H_ * W_) + p0 + tx];
    __syncthreads();
#pragma unroll
    for (int i = 0; i < 32; i += 8)
        dst[(size_t)(p0 + ty + i) * C_ + c0 + tx] = tile[tx][ty + i];
}

// ---------------- per-query: gathers, split operands, pos/neg scores, mask/qconf/gt[0:81]
// 256 threads: 4 threads per offset (32 channels each), warp-uniform quad reduction.
__global__ void __launch_bounds__(256) k_posneg(const float* __restrict__ feat1,
                                                const float* __restrict__ conf1,
                                                const float* __restrict__ conf2,
                                                const float* __restrict__ aflow,
                                                float* __restrict__ out) {
    int q   = blockIdx.x;
    int tid = threadIdx.x;
    int b = q / QB;
    int r = q % QB;
    int y = 16 + (r / GW) * 8;
    int x = 16 + (r % GW) * 8;

    __shared__ __align__(16) float f1s[C_];
    __shared__ float pos_s[NPOS];
    __shared__ int2  sxy;

    if (tid < C_) {
        // f1 gather (strided over channels)
        float f1v = feat1[(((size_t)b * C_ + tid) * H_ + y) * W_ + x];
        f1s[tid] = f1v;
        __nv_bfloat16 hi = __float2bfloat16(f1v);
        __nv_bfloat16 lo = __float2bfloat16(f1v - __bfloat162float(hi));
        __nv_bfloat16* arow = g_a + (size_t)q * KSP;
        arow[tid] = hi; arow[128 + tid] = hi; arow[256 + tid] = lo;
        // distractor feature gather (coalesced from transposed layout)
        float f2v = g_feat2t[(((size_t)b * H_ + y) * W_ + x) * C_ + tid];
        __nv_bfloat16 hi2 = __float2bfloat16(f2v);
        __nv_bfloat16 lo2 = __float2bfloat16(f2v - __bfloat162float(hi2));
        __nv_bfloat16* brow = g_b + (size_t)q * KSP;
        brow[tid] = hi2; brow[128 + tid] = lo2; brow[256 + tid] = hi2;
    }
    if (tid >= 128 && tid < 128 + 81)   // gt columns 0..80: [1, 0 x 80]
        out[S_SCORES + (size_t)q * NCOL + (tid - 128)] = (tid == 128) ? 1.0f : 0.0f;
    if (tid == 0) {
        float ax = aflow[(((size_t)b * 2 + 0) * H_ + y) * W_ + x];
        float ay = aflow[(((size_t)b * 2 + 1) * H_ + y) * W_ + x];
        int x2 = (int)(ax + 0.5f);
        int y2 = (int)(ay + 0.5f);
        sxy = make_int2(x2, y2);
        g_xy2[q] = sxy;
        bool m = (x2 >= 0) && (y2 >= 0) && (x2 < W_) && (y2 < H_);
        out[2 * S_SCORES + q] = m ? 1.0f : 0.0f;           // mask
    }
    __syncthreads();

    int2 xy2 = sxy;
    const float* f2b = g_feat2t + (size_t)b * H_ * W_ * C_;
    int co = tid & 3;                     // channel quarter
    const float4* a4 = (const float4*)f1s + co * 8;

#pragma unroll
    for (int base = 0; base < NOFF; base += 64) {
        int off_raw = base + (tid >> 2);
        int off = min(off_raw, NOFF - 1);     // clamp: keep ALL lanes active (warp-uniform shfl)
        int xx = min(max(xy2.x + c_off[off][0], 0), W_ - 1);
        int yy = min(max(xy2.y + c_off[off][1], 0), H_ - 1);
        const float4* p = (const float4*)(f2b + ((size_t)yy * W_ + xx) * C_) + co * 8;
        float s0 = 0.0f, s1 = 0.0f;
#pragma unroll
        for (int i = 0; i < 8; i += 2) {
            float4 v0 = p[i],     a0 = a4[i];
            float4 v1 = p[i + 1], a1 = a4[i + 1];
            s0 += v0.x * a0.x + v0.y * a0.y + v0.z * a0.z + v0.w * a0.w;
            s1 += v1.x * a1.x + v1.y * a1.y + v1.z * a1.z + v1.w * a1.w;
        }
        float s = s0 + s1;
        s += __shfl_xor_sync(0xffffffffu, s, 1);
        s += __shfl_xor_sync(0xffffffffu, s, 2);
        if (co == 0 && off_raw < NOFF) {
            if (off_raw < NPOS) pos_s[off_raw] = s;
            else out[(size_t)q * NCOL + 1 + (off_raw - NPOS)] = s;   // nscores
        }
    }
    __syncthreads();

    if (tid == 0) {
        // first-occurrence argmax (strict > keeps first), matching jnp.argmax
        float best = pos_s[0];
        int bi = 0;
        for (int p = 1; p < NPOS; p++)
            if (pos_s[p] > best) { best = pos_s[p]; bi = p; }
        out[(size_t)q * NCOL] = best;                          // pscores
        int sx = min(max(xy2.x + c_off[bi][0], 0), W_ - 1);
        int sy = min(max(xy2.y + c_off[bi][1], 0), H_ - 1);
        float c1 = conf1[((size_t)b * H_ + y)  * W_ + x];
        float c2 = conf2[((size_t)b * H_ + sy) * W_ + sx];
        out[2 * S_SCORES + Q_ + q] = 0.5f * (c1 + c2);         // qconf
    }
}

// ---------------- dscores GEMM: bf16 tensor cores, K=384 split, mask+gt fused
// As/Bs padded to 24 bf16 per row (48B) -> conflict-free LDSM.
#define LDP 24
__global__ void __launch_bounds__(256, 2) k_gemm(float* __restrict__ out) {
    __shared__ __align__(16) __nv_bfloat16 As[2][128][LDP];
    __shared__ __align__(16) __nv_bfloat16 Bs[2][128][LDP];
    __shared__ int scx[128], scy[128], scb[128];   // col (distractor) coords
    __shared__ int srx[128], sry[128], srb[128];   // row (query) xy2/batch

    int t  = threadIdx.x;
    int q0 = blockIdx.y * 128;
    int d0 = blockIdx.x * 128;

    if (t < 128) {
        int d = min(d0 + t, ND - 1);
        int b3 = d / QB, rd = d % QB;
        scb[t] = b3;
        scy[t] = 16 + (rd / GW) * 8;
        scx[t] = 16 + (rd % GW) * 8;
        int q = min(q0 + t, Q_ - 1);
        int2 xy = g_xy2[q];
        srx[t] = xy.x; sry[t] = xy.y; srb[t] = q / QB;
    }

    int warp = t >> 5, lane = t & 31;
    int wm = warp & 3;        // 4 warps along M (32 rows each)
    int wn = warp >> 2;       // 2 warps along N (64 cols each)
    int group = lane >> 2, tig = lane & 3;

    float acc[2][8][4];
#pragma unroll
    for (int i = 0; i < 2; i++)
#pragma unroll
        for (int j = 0; j < 8; j++)
#pragma unroll
            for (int c = 0; c < 4; c++) acc[i][j][c] = 0.0f;

    for (int kc = 0; kc < KSP; kc += 32) {
        // stage two k16 slabs of A and B
#pragma unroll
        for (int rr = 0; rr < 2; rr++) {
            int u = t + rr * 256;           // 0..511
            int row = u >> 2;
            int seg = u & 3;                // 8-element (16B) segment
            int gq = min(q0 + row, Q_ - 1);
            int gd = min(d0 + row, ND - 1);
            *(uint4*)&As[seg >> 1][row][(seg & 1) * 8] =
                *(const uint4*)&g_a[(size_t)gq * KSP + kc + seg * 8];
            *(uint4*)&Bs[seg >> 1][row][(seg & 1) * 8] =
                *(const uint4*)&g_b[(size_t)gd * KSP + kc + seg * 8];
        }
        __syncthreads();
#pragma unroll
        for (int s = 0; s < 2; s++) {
            uint32_t af[2][4], bf[4][4];
            int rsel = lane & 15;
            int csel = (lane >> 4) * 8;
#pragma unroll
            for (int i = 0; i < 2; i++)
                ldsm_x4(af[i], &As[s][wm * 32 + i * 16 + rsel][csel]);
#pragma unroll
            for (int j4 = 0; j4 < 4; j4++)
                ldsm_x4(bf[j4], &Bs[s][wn * 64 + j4 * 16 + rsel][csel]);
#pragma unroll
            for (int i = 0; i < 2; i++)
#pragma unroll
                for (int j = 0; j < 8; j++)
                    mma_bf16(acc[i][j], af[i], bf[j >> 1][j & 1], bf[j >> 1][(j & 1) + 2]);
        }
        __syncthreads();
    }

    // epilogue: distance mask -> dscores, plus gt zeros
#pragma unroll
    for (int i = 0; i < 2; i++) {
#pragma unroll
        for (int half = 0; half < 2; half++) {
            int rloc = wm * 32 + i * 16 + group + half * 8;
            int q = q0 + rloc;
            if (q >= Q_) continue;
            int qx = srx[rloc], qy = sry[rloc], qb = srb[rloc];
            float* so = out + (size_t)q * NCOL + 1 + NNEG;
            float* go = out + S_SCORES + (size_t)q * NCOL + 1 + NNEG;
#pragma unroll
            for (int j = 0; j < 8; j++) {
                int cloc = wn * 64 + j * 8 + tig * 2;
                int d = d0 + cloc;
                if (d >= ND) continue;
                int dx0 = scx[cloc] - qx,     dy0 = scy[cloc] - qy;
                int dx1 = scx[cloc + 1] - qx, dy1 = scy[cloc + 1] - qy;
                int dis0 = dx0 * dx0 + dy0 * dy0 + (scb[cloc] != qb ? 25 : 0);
                int dis1 = dx1 * dx1 + dy1 * dy1 + (scb[cloc + 1] != qb ? 25 : 0);
                so[d]     = (dis0 < 25) ? 0.0f : acc[i][j][half * 2 + 0];
                so[d + 1] = (dis1 < 25) ? 0.0f : acc[i][j][half * 2 + 1];
                go[d]     = 0.0f;
                go[d + 1] = 0.0f;
            }
        }
    }
}

// ---------------- launch ----------------
extern "C" void kernel_launch(void* const* d_in, const int* in_sizes, int n_in,
                              void* d_out, int out_size) {
    const float* feat1 = (const float*)d_in[0];
    const float* feat2 = (const float*)d_in[1];
    const float* conf1 = (const float*)d_in[2];
    const float* conf2 = (const float*)d_in[3];
    const float* aflow = (const float*)d_in[4];
    float* out = (float*)d_out;
    (void)in_sizes; (void)n_in; (void)out_size;

    dim3 tb(32, 8);
    dim3 tg((H_ * W_) / 32, C_ / 32, B_);
    k_transpose<<<tg, tb>>>(feat2);

    k_posneg<<<Q_, 256>>>(feat1, conf1, conf2, aflow, out);

    dim3 gg(MPAD / 128, MPAD / 128);
    k_gemm<<<gg, 256>>>(out);
}

// round 6
// speedup vs baseline: 1.1898x; 1.1898x over previous
#include <cuda_runtime.h>
#include <cuda_bf16.h>
#include <cstdint>

#define B_    4
#define C_    128
#define H_    256
#define W_    256
#define GW    28
#define QB    784
#define Q_    3136
#define NPOS  29
#define NNEG  80
#define NOFF  109
#define ND    3136
#define NCOL  3217   /* 1 + 80 + 3136 */
#define MPAD  3200   /* 25 * 128 */
#define KSP   384    /* 3 * 128 : [hiA|hiA|loA] x [hiB|loB|hiB] */

static const size_t S_SCORES = (size_t)Q_ * NCOL;   // 10,088,512

// ---------------- offsets, exact reference enumeration order (j outer asc, i inner asc)
__constant__ int c_off[NOFF][2] = {
    // ---- 29 positives ----
    {0,-3},
    {-2,-2},{-1,-2},{0,-2},{1,-2},{2,-2},
    {-2,-1},{-1,-1},{0,-1},{1,-1},{2,-1},
    {-3,0},{-2,0},{-1,0},{0,0},{1,0},{2,0},{3,0},
    {-2,1},{-1,1},{0,1},{1,1},{2,1},
    {-2,2},{-1,2},{0,2},{1,2},{2,2},
    {0,3},
    // ---- 80 negatives ----
    {0,-7},
    {-3,-6},{-2,-6},{-1,-6},{0,-6},{1,-6},{2,-6},{3,-6},
    {-4,-5},{-3,-5},{-2,-5},{-1,-5},{0,-5},{1,-5},{2,-5},{3,-5},{4,-5},
    {-5,-4},{-4,-4},{-3,-4},{3,-4},{4,-4},{5,-4},
    {-6,-3},{-5,-3},{-4,-3},{4,-3},{5,-3},{6,-3},
    {-6,-2},{-5,-2},{5,-2},{6,-2},
    {-6,-1},{-5,-1},{5,-1},{6,-1},
    {-7,0},{-6,0},{-5,0},{5,0},{6,0},{7,0},
    {-6,1},{-5,1},{5,1},{6,1},
    {-6,2},{-5,2},{5,2},{6,2},
    {-6,3},{-5,3},{-4,3},{4,3},{5,3},{6,3},
    {-5,4},{-4,4},{-3,4},{3,4},{4,4},{5,4},
    {-4,5},{-3,5},{-2,5},{-1,5},{0,5},{1,5},{2,5},{3,5},{4,5},
    {-3,6},{-2,6},{-1,6},{0,6},{1,6},{2,6},{3,6},
    {0,7}
};

// ---------------- device scratch ----------------
__device__ float g_feat2t[(size_t)B_ * H_ * W_ * C_];       // feat2 -> (B,H,W,C)
__device__ __nv_bfloat16 g_a[(size_t)MPAD * KSP];           // split queries
__device__ __nv_bfloat16 g_b[(size_t)MPAD * KSP];           // split distractors
__device__ int2  g_xy2[Q_];

// ---------------- helpers ----------------
__device__ __forceinline__ void ldsm_x4(uint32_t (&r)[4], const void* p) {
    uint32_t a = (uint32_t)__cvta_generic_to_shared(p);
    asm volatile("ldmatrix.sync.aligned.m8n8.x4.shared.b16 {%0,%1,%2,%3}, [%4];"
        : "=r"(r[0]), "=r"(r[1]), "=r"(r[2]), "=r"(r[3]) : "r"(a));
}
__device__ __forceinline__ void mma_bf16(float (&d)[4], const uint32_t (&a)[4],
                                         uint32_t b0, uint32_t b1) {
    asm volatile("mma.sync.aligned.m16n8k16.row.col.f32.bf16.bf16.f32 "
        "{%0,%1,%2,%3}, {%4,%5,%6,%7}, {%8,%9}, {%0,%1,%2,%3};"
        : "+f"(d[0]), "+f"(d[1]), "+f"(d[2]), "+f"(d[3])
        : "r"(a[0]), "r"(a[1]), "r"(a[2]), "r"(a[3]), "r"(b0), "r"(b1));
}

// ---------------- transpose feat2 (B,C,H,W) -> (B,HW,C)  [R2 version: best measured]
__global__ void k_transpose(const float* __restrict__ f2) {
    __shared__ float tile[32][33];
    int b  = blockIdx.z;
    int p0 = blockIdx.x * 32;     // pixel (h*W+w)
    int c0 = blockIdx.y * 32;     // channel
    int tx = threadIdx.x, ty = threadIdx.y;     // 32 x 8
    const float* src = f2 + (size_t)b * C_ * H_ * W_;
    float* dst = g_feat2t + (size_t)b * H_ * W_ * C_;
#pragma unroll
    for (int i = 0; i < 32; i += 8)
        tile[ty + i][tx] = src[(size_t)(c0 + ty + i) * (H_ * W_) + p0 + tx];
    __syncthreads();
#pragma unroll
    for (int i = 0; i < 32; i += 8)
        dst[(size_t)(p0 + ty + i) * C_ + c0 + tx] = tile[tx][ty + i];
}

// ---------------- per-query: gathers + bf16 split production, pos/neg scores,
// mask/qconf/gt[0:81].  Offsets phase: R2 structure (warp per offset, shfl tree).
__global__ void __launch_bounds__(256) k_posneg(const float* __restrict__ feat1,
                                                const float* __restrict__ conf1,
                                                const float* __restrict__ conf2,
                                                const float* __restrict__ aflow,
                                                float* __restrict__ out) {
    int q   = blockIdx.x;
    int tid = threadIdx.x;
    int b = q / QB;
    int r = q % QB;
    int y = 16 + (r / GW) * 8;
    int x = 16 + (r % GW) * 8;

    __shared__ __align__(16) float f1s[C_];
    __shared__ float pos_s[NPOS];
    __shared__ int2  sxy;

    if (tid < C_) {
        // f1 gather (strided over channels)
        float f1v = feat1[(((size_t)b * C_ + tid) * H_ + y) * W_ + x];
        f1s[tid] = f1v;
        __nv_bfloat16 hi = __float2bfloat16(f1v);
        __nv_bfloat16 lo = __float2bfloat16(f1v - __bfloat162float(hi));
        __nv_bfloat16* arow = g_a + (size_t)q * KSP;
        arow[tid] = hi; arow[128 + tid] = hi; arow[256 + tid] = lo;
        // distractor feature gather (coalesced from transposed layout)
        float f2v = g_feat2t[(((size_t)b * H_ + y) * W_ + x) * C_ + tid];
        __nv_bfloat16 hi2 = __float2bfloat16(f2v);
        __nv_bfloat16 lo2 = __float2bfloat16(f2v - __bfloat162float(hi2));
        __nv_bfloat16* brow = g_b + (size_t)q * KSP;
        brow[tid] = hi2; brow[128 + tid] = lo2; brow[256 + tid] = hi2;
    }
    if (tid >= 128 && tid < 128 + 81)   // gt columns 0..80: [1, 0 x 80]
        out[S_SCORES + (size_t)q * NCOL + (tid - 128)] = (tid == 128) ? 1.0f : 0.0f;
    if (tid == 0) {
        float ax = aflow[(((size_t)b * 2 + 0) * H_ + y) * W_ + x];
        float ay = aflow[(((size_t)b * 2 + 1) * H_ + y) * W_ + x];
        int x2 = (int)(ax + 0.5f);
        int y2 = (int)(ay + 0.5f);
        sxy = make_int2(x2, y2);
        g_xy2[q] = sxy;
        bool m = (x2 >= 0) && (y2 >= 0) && (x2 < W_) && (y2 < H_);
        out[2 * S_SCORES + q] = m ? 1.0f : 0.0f;           // mask
    }
    __syncthreads();

    int2 xy2 = sxy;
    int lane = tid & 31, warp = tid >> 5;    // 8 warps, warp-uniform loop
    const float* f2b = g_feat2t + (size_t)b * H_ * W_ * C_;
    const float4* f1v4 = (const float4*)f1s;
    float4 a = f1v4[lane];                   // lane owns channels 4*lane..4*lane+3

    for (int idx = warp; idx < NOFF; idx += 8) {
        int ox = c_off[idx][0], oy = c_off[idx][1];
        int xx = min(max(xy2.x + ox, 0), W_ - 1);
        int yy = min(max(xy2.y + oy, 0), H_ - 1);
        const float4* p = (const float4*)(f2b + ((size_t)yy * W_ + xx) * C_);
        float4 v = p[lane];
        float s = v.x * a.x + v.y * a.y + v.z * a.z + v.w * a.w;
        s += __shfl_xor_sync(0xffffffffu, s, 16);
        s += __shfl_xor_sync(0xffffffffu, s, 8);
        s += __shfl_xor_sync(0xffffffffu, s, 4);
        s += __shfl_xor_sync(0xffffffffu, s, 2);
        s += __shfl_xor_sync(0xffffffffu, s, 1);
        if (lane == 0) {
            if (idx < NPOS) pos_s[idx] = s;
            else out[(size_t)q * NCOL + 1 + (idx - NPOS)] = s;   // nscores
        }
    }
    __syncthreads();

    if (tid == 0) {
        // first-occurrence argmax (strict > keeps first), matching jnp.argmax
        float best = pos_s[0];
        int bi = 0;
        for (int p = 1; p < NPOS; p++)
            if (pos_s[p] > best) { best = pos_s[p]; bi = p; }
        out[(size_t)q * NCOL] = best;                          // pscores
        int sx = min(max(xy2.x + c_off[bi][0], 0), W_ - 1);
        int sy = min(max(xy2.y + c_off[bi][1], 0), H_ - 1);
        float c1 = conf1[((size_t)b * H_ + y)  * W_ + x];
        float c2 = conf2[((size_t)b * H_ + sy) * W_ + sx];
        out[2 * S_SCORES + Q_ + q] = 0.5f * (c1 + c2);         // qconf
    }
}

// ---------------- dscores GEMM: bf16 tensor cores, K=384 split, mask+gt fused
// As/Bs padded to 24 bf16 per row (48B) -> conflict-free LDSM.
#define LDP 24
__global__ void __launch_bounds__(256, 2) k_gemm(float* __restrict__ out) {
    __shared__ __align__(16) __nv_bfloat16 As[2][128][LDP];
    __shared__ __align__(16) __nv_bfloat16 Bs[2][128][LDP];
    __shared__ int scx[128], scy[128], scb[128];   // col (distractor) coords
    __shared__ int srx[128], sry[128], srb[128];   // row (query) xy2/batch

    int t  = threadIdx.x;
    int q0 = blockIdx.y * 128;
    int d0 = blockIdx.x * 128;

    if (t < 128) {
        int d = min(d0 + t, ND - 1);
        int b3 = d / QB, rd = d % QB;
        scb[t] = b3;
        scy[t] = 16 + (rd / GW) * 8;
        scx[t] = 16 + (rd % GW) * 8;
        int q = min(q0 + t, Q_ - 1);
        int2 xy = g_xy2[q];
        srx[t] = xy.x; sry[t] = xy.y; srb[t] = q / QB;
    }

    int warp = t >> 5, lane = t & 31;
    int wm = warp & 3;        // 4 warps along M (32 rows each)
    int wn = warp >> 2;       // 2 warps along N (64 cols each)
    int group = lane >> 2, tig = lane & 3;

    float acc[2][8][4];
#pragma unroll
    for (int i = 0; i < 2; i++)
#pragma unroll
        for (int j = 0; j < 8; j++)
#pragma unroll
            for (int c = 0; c < 4; c++) acc[i][j][c] = 0.0f;

    for (int kc = 0; kc < KSP; kc += 32) {
        // stage two k16 slabs of A and B
#pragma unroll
        for (int rr = 0; rr < 2; rr++) {
            int u = t + rr * 256;           // 0..511
            int row = u >> 2;
            int seg = u & 3;                // 8-element (16B) segment
            int gq = min(q0 + row, Q_ - 1);
            int gd = min(d0 + row, ND - 1);
            *(uint4*)&As[seg >> 1][row][(seg & 1) * 8] =
                *(const uint4*)&g_a[(size_t)gq * KSP + kc + seg * 8];
            *(uint4*)&Bs[seg >> 1][row][(seg & 1) * 8] =
                *(const uint4*)&g_b[(size_t)gd * KSP + kc + seg * 8];
        }
        __syncthreads();
#pragma unroll
        for (int s = 0; s < 2; s++) {
            uint32_t af[2][4], bf[4][4];
            int rsel = lane & 15;
            int csel = (lane >> 4) * 8;
#pragma unroll
            for (int i = 0; i < 2; i++)
                ldsm_x4(af[i], &As[s][wm * 32 + i * 16 + rsel][csel]);
#pragma unroll
            for (int j4 = 0; j4 < 4; j4++)
                ldsm_x4(bf[j4], &Bs[s][wn * 64 + j4 * 16 + rsel][csel]);
#pragma unroll
            for (int i = 0; i < 2; i++)
#pragma unroll
                for (int j = 0; j < 8; j++)
                    mma_bf16(acc[i][j], af[i], bf[j >> 1][j & 1], bf[j >> 1][(j & 1) + 2]);
        }
        __syncthreads();
    }

    // epilogue: distance mask -> dscores, plus gt zeros
#pragma unroll
    for (int i = 0; i < 2; i++) {
#pragma unroll
        for (int half = 0; half < 2; half++) {
            int rloc = wm * 32 + i * 16 + group + half * 8;
            int q = q0 + rloc;
            if (q >= Q_) continue;
            int qx = srx[rloc], qy = sry[rloc], qb = srb[rloc];
            float* so = out + (size_t)q * NCOL + 1 + NNEG;
            float* go = out + S_SCORES + (size_t)q * NCOL + 1 + NNEG;
#pragma unroll
            for (int j = 0; j < 8; j++) {
                int cloc = wn * 64 + j * 8 + tig * 2;
                int d = d0 + cloc;
                if (d >= ND) continue;
                int dx0 = scx[cloc] - qx,     dy0 = scy[cloc] - qy;
                int dx1 = scx[cloc + 1] - qx, dy1 = scy[cloc + 1] - qy;
                int dis0 = dx0 * dx0 + dy0 * dy0 + (scb[cloc] != qb ? 25 : 0);
                int dis1 = dx1 * dx1 + dy1 * dy1 + (scb[cloc + 1] != qb ? 25 : 0);
                so[d]     = (dis0 < 25) ? 0.0f : acc[i][j][half * 2 + 0];
                so[d + 1] = (dis1 < 25) ? 0.0f : acc[i][j][half * 2 + 1];
                go[d]     = 0.0f;
                go[d + 1] = 0.0f;
            }
        }
    }
}

// ---------------- launch ----------------
extern "C" void kernel_launch(void* const* d_in, const int* in_sizes, int n_in,
                              void* d_out, int out_size) {
    const float* feat1 = (const float*)d_in[0];
    const float* feat2 = (const float*)d_in[1];
    const float* conf1 = (const float*)d_in[2];
    const float* conf2 = (const float*)d_in[3];
    const float* aflow = (const float*)d_in[4];
    float* out = (float*)d_out;
    (void)in_sizes; (void)n_in; (void)out_size;

    dim3 tb(32, 8);
    dim3 tg((H_ * W_) / 32, C_ / 32, B_);
    k_transpose<<<tg, tb>>>(feat2);

    k_posneg<<<Q_, 256>>>(feat1, conf1, conf2, aflow, out);

    dim3 gg(MPAD / 128, MPAD / 128);
    k_gemm<<<gg, 256>>>(out);
}

// round 7
// speedup vs baseline: 1.4156x; 1.1897x over previous
#include <cuda_runtime.h>
#include <cuda_bf16.h>
#include <cstdint>

#define B_    4
#define C_    128
#define H_    256
#define W_    256
#define GW    28
#define QB    784
#define Q_    3136
#define NPOS  29
#define NNEG  80
#define NOFF  109
#define ND    3136
#define NCOL  3217   /* 1 + 80 + 3136 */
#define MPAD  3200   /* 25 * 128 */
#define KSP   384    /* 3 * 128 : [hiA|hiA|loA] x [hiB|loB|hiB] */

static const size_t S_SCORES = (size_t)Q_ * NCOL;   // 10,088,512

// ---------------- offsets, exact reference enumeration order (j outer asc, i inner asc)
__constant__ int c_off[NOFF][2] = {
    // ---- 29 positives ----
    {0,-3},
    {-2,-2},{-1,-2},{0,-2},{1,-2},{2,-2},
    {-2,-1},{-1,-1},{0,-1},{1,-1},{2,-1},
    {-3,0},{-2,0},{-1,0},{0,0},{1,0},{2,0},{3,0},
    {-2,1},{-1,1},{0,1},{1,1},{2,1},
    {-2,2},{-1,2},{0,2},{1,2},{2,2},
    {0,3},
    // ---- 80 negatives ----
    {0,-7},
    {-3,-6},{-2,-6},{-1,-6},{0,-6},{1,-6},{2,-6},{3,-6},
    {-4,-5},{-3,-5},{-2,-5},{-1,-5},{0,-5},{1,-5},{2,-5},{3,-5},{4,-5},
    {-5,-4},{-4,-4},{-3,-4},{3,-4},{4,-4},{5,-4},
    {-6,-3},{-5,-3},{-4,-3},{4,-3},{5,-3},{6,-3},
    {-6,-2},{-5,-2},{5,-2},{6,-2},
    {-6,-1},{-5,-1},{5,-1},{6,-1},
    {-7,0},{-6,0},{-5,0},{5,0},{6,0},{7,0},
    {-6,1},{-5,1},{5,1},{6,1},
    {-6,2},{-5,2},{5,2},{6,2},
    {-6,3},{-5,3},{-4,3},{4,3},{5,3},{6,3},
    {-5,4},{-4,4},{-3,4},{3,4},{4,4},{5,4},
    {-4,5},{-3,5},{-2,5},{-1,5},{0,5},{1,5},{2,5},{3,5},{4,5},
    {-3,6},{-2,6},{-1,6},{0,6},{1,6},{2,6},{3,6},
    {0,7}
};

// ---------------- device scratch ----------------
__device__ float g_feat2t[(size_t)B_ * H_ * W_ * C_];       // feat2 -> (B,H,W,C)
__device__ __nv_bfloat16 g_a[(size_t)MPAD * KSP];           // split queries
__device__ __nv_bfloat16 g_b[(size_t)MPAD * KSP];           // split distractors
__device__ int2  g_xy2[Q_];

// ---------------- helpers ----------------
__device__ __forceinline__ void ldsm_x4(uint32_t (&r)[4], const void* p) {
    uint32_t a = (uint32_t)__cvta_generic_to_shared(p);
    asm volatile("ldmatrix.sync.aligned.m8n8.x4.shared.b16 {%0,%1,%2,%3}, [%4];"
        : "=r"(r[0]), "=r"(r[1]), "=r"(r[2]), "=r"(r[3]) : "r"(a));
}
__device__ __forceinline__ void mma_bf16(float (&d)[4], const uint32_t (&a)[4],
                                         uint32_t b0, uint32_t b1) {
    asm volatile("mma.sync.aligned.m16n8k16.row.col.f32.bf16.bf16.f32 "
        "{%0,%1,%2,%3}, {%4,%5,%6,%7}, {%8,%9}, {%0,%1,%2,%3};"
        : "+f"(d[0]), "+f"(d[1]), "+f"(d[2]), "+f"(d[3])
        : "r"(a[0]), "r"(a[1]), "r"(a[2]), "r"(a[3]), "r"(b0), "r"(b1));
}

// ---------------- transpose feat2 (B,C,H,W) -> (B,HW,C), 64-pixel tiles ----------------
__global__ void k_transpose(const float* __restrict__ f2) {
    __shared__ float tile[32][65];
    int b  = blockIdx.z;
    int p0 = blockIdx.x * 64;     // pixel (h*W+w)
    int c0 = blockIdx.y * 32;     // channel
    int tx = threadIdx.x, ty = threadIdx.y;     // 32 x 8
    const float* src = f2 + (size_t)b * C_ * H_ * W_;
    float* dst = g_feat2t + (size_t)b * H_ * W_ * C_;
#pragma unroll
    for (int i = 0; i < 32; i += 8) {
        tile[ty + i][tx]      = src[(size_t)(c0 + ty + i) * (H_ * W_) + p0 + tx];
        tile[ty + i][tx + 32] = src[(size_t)(c0 + ty + i) * (H_ * W_) + p0 + 32 + tx];
    }
    __syncthreads();
#pragma unroll
    for (int i = 0; i < 8; i++)
        dst[(size_t)(p0 + ty + 8 * i) * C_ + c0 + tx] = tile[tx][ty + 8 * i];
}

// ---------------- per-query: gathers + bf16 split production, pos/neg scores,
// mask/qconf/gt[0:81].  Offsets phase: warp per offset, depth-2 prefetch pipeline.
__global__ void __launch_bounds__(256) k_posneg(const float* __restrict__ feat1,
                                                const float* __restrict__ conf1,
                                                const float* __restrict__ conf2,
                                                const float* __restrict__ aflow,
                                                float* __restrict__ out) {
    int q   = blockIdx.x;
    int tid = threadIdx.x;
    int b = q / QB;
    int r = q % QB;
    int y = 16 + (r / GW) * 8;
    int x = 16 + (r % GW) * 8;

    __shared__ __align__(16) float f1s[C_];
    __shared__ float pos_s[NPOS];
    __shared__ int2  sxy;

    if (tid < C_) {
        // f1 gather (strided over channels)
        float f1v = feat1[(((size_t)b * C_ + tid) * H_ + y) * W_ + x];
        f1s[tid] = f1v;
        __nv_bfloat16 hi = __float2bfloat16(f1v);
        __nv_bfloat16 lo = __float2bfloat16(f1v - __bfloat162float(hi));
        __nv_bfloat16* arow = g_a + (size_t)q * KSP;
        arow[tid] = hi; arow[128 + tid] = hi; arow[256 + tid] = lo;
        // distractor feature gather (coalesced from transposed layout)
        float f2v = g_feat2t[(((size_t)b * H_ + y) * W_ + x) * C_ + tid];
        __nv_bfloat16 hi2 = __float2bfloat16(f2v);
        __nv_bfloat16 lo2 = __float2bfloat16(f2v - __bfloat162float(hi2));
        __nv_bfloat16* brow = g_b + (size_t)q * KSP;
        brow[tid] = hi2; brow[128 + tid] = lo2; brow[256 + tid] = hi2;
    }
    if (tid >= 128 && tid < 128 + 81)   // gt columns 0..80: [1, 0 x 80]
        out[S_SCORES + (size_t)q * NCOL + (tid - 128)] = (tid == 128) ? 1.0f : 0.0f;
    if (tid == 0) {
        float ax = aflow[(((size_t)b * 2 + 0) * H_ + y) * W_ + x];
        float ay = aflow[(((size_t)b * 2 + 1) * H_ + y) * W_ + x];
        int x2 = (int)(ax + 0.5f);
        int y2 = (int)(ay + 0.5f);
        sxy = make_int2(x2, y2);
        g_xy2[q] = sxy;
        bool m = (x2 >= 0) && (y2 >= 0) && (x2 < W_) && (y2 < H_);
        out[2 * S_SCORES + q] = m ? 1.0f : 0.0f;           // mask
    }
    __syncthreads();

    int2 xy2 = sxy;
    int lane = tid & 31, warp = tid >> 5;    // 8 warps, warp-uniform loop
    const float* f2b = g_feat2t + (size_t)b * H_ * W_ * C_;
    const float4* f1v4 = (const float4*)f1s;
    float4 a = f1v4[lane];                   // lane owns channels 4*lane..4*lane+3

    // depth-2 prefetch pipeline over offsets (all conditions warp-uniform)
    float4 v0, v1;
    {
        int xx = min(max(xy2.x + c_off[warp][0], 0), W_ - 1);
        int yy = min(max(xy2.y + c_off[warp][1], 0), H_ - 1);
        v0 = ((const float4*)(f2b + ((size_t)yy * W_ + xx) * C_))[lane];
    }
    if (warp + 8 < NOFF) {
        int xx = min(max(xy2.x + c_off[warp + 8][0], 0), W_ - 1);
        int yy = min(max(xy2.y + c_off[warp + 8][1], 0), H_ - 1);
        v1 = ((const float4*)(f2b + ((size_t)yy * W_ + xx) * C_))[lane];
    }
    for (int idx = warp; idx < NOFF; idx += 8) {
        int nn = idx + 16;
        float4 vn;
        if (nn < NOFF) {
            int xx = min(max(xy2.x + c_off[nn][0], 0), W_ - 1);
            int yy = min(max(xy2.y + c_off[nn][1], 0), H_ - 1);
            vn = ((const float4*)(f2b + ((size_t)yy * W_ + xx) * C_))[lane];
        }
        float s = v0.x * a.x + v0.y * a.y + v0.z * a.z + v0.w * a.w;
        s += __shfl_xor_sync(0xffffffffu, s, 16);
        s += __shfl_xor_sync(0xffffffffu, s, 8);
        s += __shfl_xor_sync(0xffffffffu, s, 4);
        s += __shfl_xor_sync(0xffffffffu, s, 2);
        s += __shfl_xor_sync(0xffffffffu, s, 1);
        if (lane == 0) {
            if (idx < NPOS) pos_s[idx] = s;
            else out[(size_t)q * NCOL + 1 + (idx - NPOS)] = s;   // nscores
        }
        v0 = v1; v1 = vn;
    }
    __syncthreads();

    if (tid == 0) {
        // first-occurrence argmax (strict > keeps first), matching jnp.argmax
        float best = pos_s[0];
        int bi = 0;
        for (int p = 1; p < NPOS; p++)
            if (pos_s[p] > best) { best = pos_s[p]; bi = p; }
        out[(size_t)q * NCOL] = best;                          // pscores
        int sx = min(max(xy2.x + c_off[bi][0], 0), W_ - 1);
        int sy = min(max(xy2.y + c_off[bi][1], 0), H_ - 1);
        float c1 = conf1[((size_t)b * H_ + y)  * W_ + x];
        float c2 = conf2[((size_t)b * H_ + sy) * W_ + sx];
        out[2 * S_SCORES + Q_ + q] = 0.5f * (c1 + c2);         // qconf
    }
}

// ---------------- dscores GEMM: bf16 tensor cores, K=384 split, mask+gt fused
// As/Bs padded to 24 bf16 per row (48B). Epilogue staged through smem for
// lane-contiguous global stores.
#define LDP 24
__global__ void __launch_bounds__(256) k_gemm(float* __restrict__ out) {
    __shared__ __align__(16) __nv_bfloat16 As[2][128][LDP];
    __shared__ __align__(16) __nv_bfloat16 Bs[2][128][LDP];
    __shared__ float sbuf[32][132];                 // epilogue staging
    __shared__ int scx[128], scy[128], scb[128];    // col (distractor) coords
    __shared__ int srx[128], sry[128], srb[128];    // row (query) xy2/batch

    int t  = threadIdx.x;
    int q0 = blockIdx.y * 128;
    int d0 = blockIdx.x * 128;

    if (t < 128) {
        int d = min(d0 + t, ND - 1);
        int b3 = d / QB, rd = d % QB;
        scb[t] = b3;
        scy[t] = 16 + (rd / GW) * 8;
        scx[t] = 16 + (rd % GW) * 8;
        int q = min(q0 + t, Q_ - 1);
        int2 xy = g_xy2[q];
        srx[t] = xy.x; sry[t] = xy.y; srb[t] = q / QB;
    }

    int warp = t >> 5, lane = t & 31;
    int wm = warp & 3;        // 4 warps along M (32 rows each)
    int wn = warp >> 2;       // 2 warps along N (64 cols each)

    float acc[2][8][4];
#pragma unroll
    for (int i = 0; i < 2; i++)
#pragma unroll
        for (int j = 0; j < 8; j++)
#pragma unroll
            for (int c = 0; c < 4; c++) acc[i][j][c] = 0.0f;

    for (int kc = 0; kc < KSP; kc += 32) {
        // stage two k16 slabs of A and B
#pragma unroll
        for (int rr = 0; rr < 2; rr++) {
            int u = t + rr * 256;           // 0..511
            int row = u >> 2;
            int seg = u & 3;                // 8-element (16B) segment
            int gq = min(q0 + row, Q_ - 1);
            int gd = min(d0 + row, ND - 1);
            *(uint4*)&As[seg >> 1][row][(seg & 1) * 8] =
                *(const uint4*)&g_a[(size_t)gq * KSP + kc + seg * 8];
            *(uint4*)&Bs[seg >> 1][row][(seg & 1) * 8] =
                *(const uint4*)&g_b[(size_t)gd * KSP + kc + seg * 8];
        }
        __syncthreads();
#pragma unroll
        for (int s = 0; s < 2; s++) {
            uint32_t af[2][4], bf[4][4];
            int rsel = lane & 15;
            int csel = (lane >> 4) * 8;
#pragma unroll
            for (int i = 0; i < 2; i++)
                ldsm_x4(af[i], &As[s][wm * 32 + i * 16 + rsel][csel]);
#pragma unroll
            for (int j4 = 0; j4 < 4; j4++)
                ldsm_x4(bf[j4], &Bs[s][wn * 64 + j4 * 16 + rsel][csel]);
#pragma unroll
            for (int i = 0; i < 2; i++)
#pragma unroll
                for (int j = 0; j < 8; j++)
                    mma_bf16(acc[i][j], af[i], bf[j >> 1][j & 1], bf[j >> 1][(j & 1) + 2]);
        }
        __syncthreads();
    }

    // epilogue: 4 chunks of 32 rows; stage via smem, emit lane-contiguous stores
    int group = lane >> 2, tig = lane & 3;
#pragma unroll 1
    for (int w = 0; w < 4; w++) {
        if (wm == w) {
#pragma unroll
            for (int i = 0; i < 2; i++)
#pragma unroll
                for (int j = 0; j < 8; j++)
#pragma unroll
                    for (int c = 0; c < 4; c++) {
                        int rl = i * 16 + group + (c >> 1) * 8;
                        int cl = wn * 64 + j * 8 + tig * 2 + (c & 1);
                        sbuf[rl][cl] = acc[i][j][c];
                    }
        }
        __syncthreads();
        // readout: each warp owns 4 rows; lanes contiguous over columns
#pragma unroll
        for (int r4 = 0; r4 < 4; r4++) {
            int rl = warp * 4 + r4;
            int q  = q0 + w * 32 + rl;
            if (q < Q_) {
                int qx = srx[w * 32 + rl], qy = sry[w * 32 + rl], qb = srb[w * 32 + rl];
                float* so = out + (size_t)q * NCOL + 1 + NNEG;
                float* go = out + S_SCORES + (size_t)q * NCOL + 1 + NNEG;
#pragma unroll
                for (int c4 = 0; c4 < 4; c4++) {
                    int col = c4 * 32 + lane;
                    int d = d0 + col;
                    if (d0 + c4 * 32 < ND) {       // chunk-uniform validity (32 | ND-d0)
                        int dx = scx[col] - qx, dy = scy[col] - qy;
                        int dis2 = dx * dx + dy * dy + (scb[col] != qb ? 25 : 0);
                        so[d] = (dis2 < 25) ? 0.0f : sbuf[rl][col];
                        go[d] = 0.0f;
                    }
                }
            }
        }
        __syncthreads();
    }
}

// ---------------- launch ----------------
extern "C" void kernel_launch(void* const* d_in, const int* in_sizes, int n_in,
                              void* d_out, int out_size) {
    const float* feat1 = (const float*)d_in[0];
    const float* feat2 = (const float*)d_in[1];
    const float* conf1 = (const float*)d_in[2];
    const float* conf2 = (const float*)d_in[3];
    const float* aflow = (const float*)d_in[4];
    float* out = (float*)d_out;
    (void)in_sizes; (void)n_in; (void)out_size;

    dim3 tb(32, 8);
    dim3 tg((H_ * W_) / 64, C_ / 32, B_);
    k_transpose<<<tg, tb>>>(feat2);

    k_posneg<<<Q_, 256>>>(feat1, conf1, conf2, aflow, out);

    dim3 gg(MPAD / 128, MPAD / 128);
    k_gemm<<<gg, 256>>>(out);
}

// round 9
// speedup vs baseline: 1.4325x; 1.0120x over previous
#include <cuda_runtime.h>
#include <cuda_bf16.h>
#include <cstdint>

#define B_    4
#define C_    128
#define H_    256
#define W_    256
#define GW    28
#define QB    784
#define Q_    3136
#define NPOS  29
#define NNEG  80
#define NOFF  109
#define ND    3136
#define NCOL  3217   /* 1 + 80 + 3136 */
#define MPAD  3200   /* 25 * 128 */
#define KSP   384    /* 3 * 128 : [hiA|hiA|loA] x [hiB|loB|hiB] */

static const size_t S_SCORES = (size_t)Q_ * NCOL;   // 10,088,512

// ---------------- offsets, exact reference enumeration order (j outer asc, i inner asc)
__constant__ int c_off[NOFF][2] = {
    // ---- 29 positives ----
    {0,-3},
    {-2,-2},{-1,-2},{0,-2},{1,-2},{2,-2},
    {-2,-1},{-1,-1},{0,-1},{1,-1},{2,-1},
    {-3,0},{-2,0},{-1,0},{0,0},{1,0},{2,0},{3,0},
    {-2,1},{-1,1},{0,1},{1,1},{2,1},
    {-2,2},{-1,2},{0,2},{1,2},{2,2},
    {0,3},
    // ---- 80 negatives ----
    {0,-7},
    {-3,-6},{-2,-6},{-1,-6},{0,-6},{1,-6},{2,-6},{3,-6},
    {-4,-5},{-3,-5},{-2,-5},{-1,-5},{0,-5},{1,-5},{2,-5},{3,-5},{4,-5},
    {-5,-4},{-4,-4},{-3,-4},{3,-4},{4,-4},{5,-4},
    {-6,-3},{-5,-3},{-4,-3},{4,-3},{5,-3},{6,-3},
    {-6,-2},{-5,-2},{5,-2},{6,-2},
    {-6,-1},{-5,-1},{5,-1},{6,-1},
    {-7,0},{-6,0},{-5,0},{5,0},{6,0},{7,0},
    {-6,1},{-5,1},{5,1},{6,1},
    {-6,2},{-5,2},{5,2},{6,2},
    {-6,3},{-5,3},{-4,3},{4,3},{5,3},{6,3},
    {-5,4},{-4,4},{-3,4},{3,4},{4,4},{5,4},
    {-4,5},{-3,5},{-2,5},{-1,5},{0,5},{1,5},{2,5},{3,5},{4,5},
    {-3,6},{-2,6},{-1,6},{0,6},{1,6},{2,6},{3,6},
    {0,7}
};

// ---------------- device scratch ----------------
__device__ float g_feat2t[(size_t)B_ * H_ * W_ * C_];       // feat2 -> (B,H,W,C)
__device__ __nv_bfloat16 g_a[(size_t)MPAD * KSP];           // split queries
__device__ __nv_bfloat16 g_b[(size_t)MPAD * KSP];           // split distractors
__device__ int2  g_xy2[Q_];

// ---------------- helpers ----------------
__device__ __forceinline__ void ldsm_x4(uint32_t (&r)[4], const void* p) {
    uint32_t a = (uint32_t)__cvta_generic_to_shared(p);
    asm volatile("ldmatrix.sync.aligned.m8n8.x4.shared.b16 {%0,%1,%2,%3}, [%4];"
        : "=r"(r[0]), "=r"(r[1]), "=r"(r[2]), "=r"(r[3]) : "r"(a));
}
__device__ __forceinline__ void mma_bf16(float (&d)[4], const uint32_t (&a)[4],
                                         uint32_t b0, uint32_t b1) {
    asm volatile("mma.sync.aligned.m16n8k16.row.col.f32.bf16.bf16.f32 "
        "{%0,%1,%2,%3}, {%4,%5,%6,%7}, {%8,%9}, {%0,%1,%2,%3};"
        : "+f"(d[0]), "+f"(d[1]), "+f"(d[2]), "+f"(d[3])
        : "r"(a[0]), "r"(a[1]), "r"(a[2]), "r"(a[3]), "r"(b0), "r"(b1));
}

// ---------------- transpose feat2 (B,C,H,W) -> (B,HW,C), 64-pixel tiles ----------------
__global__ void k_transpose(const float* __restrict__ f2) {
    __shared__ float tile[32][65];
    int b  = blockIdx.z;
    int p0 = blockIdx.x * 64;     // pixel (h*W+w)
    int c0 = blockIdx.y * 32;     // channel
    int tx = threadIdx.x, ty = threadIdx.y;     // 32 x 8
    const float* src = f2 + (size_t)b * C_ * H_ * W_;
    float* dst = g_feat2t + (size_t)b * H_ * W_ * C_;
#pragma unroll
    for (int i = 0; i < 32; i += 8) {
        tile[ty + i][tx]      = src[(size_t)(c0 + ty + i) * (H_ * W_) + p0 + tx];
        tile[ty + i][tx + 32] = src[(size_t)(c0 + ty + i) * (H_ * W_) + p0 + 32 + tx];
    }
    __syncthreads();
#pragma unroll
    for (int i = 0; i < 8; i++)
        dst[(size_t)(p0 + ty + 8 * i) * C_ + c0 + tx] = tile[tx][ty + 8 * i];
}

// ---------------- per-query: gathers + bf16 split production, pos/neg scores,
// mask/qconf/gt[0:81].  Offsets phase: 2 offsets per warp iteration, independent
// reduction trees (ILP 2), depth-1 pair prefetch. All shuffles warp-uniform.
__global__ void __launch_bounds__(256) k_posneg(const float* __restrict__ feat1,
                                                const float* __restrict__ conf1,
                                                const float* __restrict__ conf2,
                                                const float* __restrict__ aflow,
                                                float* __restrict__ out) {
    int q   = blockIdx.x;
    int tid = threadIdx.x;
    int b = q / QB;
    int r = q % QB;
    int y = 16 + (r / GW) * 8;
    int x = 16 + (r % GW) * 8;

    __shared__ __align__(16) float f1s[C_];
    __shared__ float pos_s[NPOS];
    __shared__ int2  sxy;

    if (tid < C_) {
        // f1 gather (strided over channels)
        float f1v = feat1[(((size_t)b * C_ + tid) * H_ + y) * W_ + x];
        f1s[tid] = f1v;
        __nv_bfloat16 hi = __float2bfloat16(f1v);
        __nv_bfloat16 lo = __float2bfloat16(f1v - __bfloat162float(hi));
        __nv_bfloat16* arow = g_a + (size_t)q * KSP;
        arow[tid] = hi; arow[128 + tid] = hi; arow[256 + tid] = lo;
        // distractor feature gather (coalesced from transposed layout)
        float f2v = g_feat2t[(((size_t)b * H_ + y) * W_ + x) * C_ + tid];
        __nv_bfloat16 hi2 = __float2bfloat16(f2v);
        __nv_bfloat16 lo2 = __float2bfloat16(f2v - __bfloat162float(hi2));
        __nv_bfloat16* brow = g_b + (size_t)q * KSP;
        brow[tid] = hi2; brow[128 + tid] = lo2; brow[256 + tid] = hi2;
    }
    if (tid >= 128 && tid < 128 + 81)   // gt columns 0..80: [1, 0 x 80]
        out[S_SCORES + (size_t)q * NCOL + (tid - 128)] = (tid == 128) ? 1.0f : 0.0f;
    if (tid == 0) {
        float ax = aflow[(((size_t)b * 2 + 0) * H_ + y) * W_ + x];
        float ay = aflow[(((size_t)b * 2 + 1) * H_ + y) * W_ + x];
        int x2 = (int)(ax + 0.5f);
        int y2 = (int)(ay + 0.5f);
        sxy = make_int2(x2, y2);
        g_xy2[q] = sxy;
        bool m = (x2 >= 0) && (y2 >= 0) && (x2 < W_) && (y2 < H_);
        out[2 * S_SCORES + q] = m ? 1.0f : 0.0f;           // mask
    }
    __syncthreads();

    int2 xy2 = sxy;
    int lane = tid & 31, warp = tid >> 5;    // 8 warps
    const float* f2b = g_feat2t + (size_t)b * H_ * W_ * C_;
    const float4* f1v4 = (const float4*)f1s;
    float4 a = f1v4[lane];                   // lane owns channels 4*lane..4*lane+3

    // warp w handles offset pairs {16*i + 2w, 16*i + 2w + 1}, i = 0..6
    #define GADDR(off) ((const float4*)(f2b + ((size_t)min(max(xy2.y + c_off[min((off), NOFF-1)][1], 0), H_ - 1) * W_ \
                         + min(max(xy2.x + c_off[min((off), NOFF-1)][0], 0), W_ - 1)) * C_) + lane)
    float4 v0 = *GADDR(2 * warp);
    float4 v1 = *GADDR(2 * warp + 1);
#pragma unroll
    for (int i = 0; i < 7; i++) {
        int o0 = 16 * i + 2 * warp;
        float4 n0, n1;
        if (i < 6) {
            n0 = *GADDR(o0 + 16);
            n1 = *GADDR(o0 + 17);
        }
        float s0 = v0.x * a.x + v0.y * a.y + v0.z * a.z + v0.w * a.w;
        float s1 = v1.x * a.x + v1.y * a.y + v1.z * a.z + v1.w * a.w;
        s0 += __shfl_xor_sync(0xffffffffu, s0, 16);
        s1 += __shfl_xor_sync(0xffffffffu, s1, 16);
        s0 += __shfl_xor_sync(0xffffffffu, s0, 8);
        s1 += __shfl_xor_sync(0xffffffffu, s1, 8);
        s0 += __shfl_xor_sync(0xffffffffu, s0, 4);
        s1 += __shfl_xor_sync(0xffffffffu, s1, 4);
        s0 += __shfl_xor_sync(0xffffffffu, s0, 2);
        s1 += __shfl_xor_sync(0xffffffffu, s1, 2);
        s0 += __shfl_xor_sync(0xffffffffu, s0, 1);
        s1 += __shfl_xor_sync(0xffffffffu, s1, 1);
        if (lane == 0) {
            if (o0 < NOFF) {
                if (o0 < NPOS) pos_s[o0] = s0;
                else out[(size_t)q * NCOL + 1 + (o0 - NPOS)] = s0;
            }
            if (o0 + 1 < NOFF) {
                if (o0 + 1 < NPOS) pos_s[o0 + 1] = s1;
                else out[(size_t)q * NCOL + 1 + (o0 + 1 - NPOS)] = s1;
            }
        }
        v0 = n0; v1 = n1;
    }
    #undef GADDR
    __syncthreads();

    if (tid == 0) {
        // first-occurrence argmax (strict > keeps first), matching jnp.argmax
        float best = pos_s[0];
        int bi = 0;
        for (int p = 1; p < NPOS; p++)
            if (pos_s[p] > best) { best = pos_s[p]; bi = p; }
        out[(size_t)q * NCOL] = best;                          // pscores
        int sx = min(max(xy2.x + c_off[bi][0], 0), W_ - 1);
        int sy = min(max(xy2.y + c_off[bi][1], 0), H_ - 1);
        float c1 = conf1[((size_t)b * H_ + y)  * W_ + x];
        float c2 = conf2[((size_t)b * H_ + sy) * W_ + sx];
        out[2 * S_SCORES + Q_ + q] = 0.5f * (c1 + c2);         // qconf
    }
}

// ---------------- dscores GEMM: bf16 tensor cores, K=384 split, mask+gt fused
// As/Bs padded to 24 bf16 per row (48B). Register-prefetch double buffering of
// the K-chunk staging; epilogue staged through smem for coalesced stores.
#define LDP 24
__global__ void __launch_bounds__(256) k_gemm(float* __restrict__ out) {
    __shared__ __align__(16) __nv_bfloat16 As[2][128][LDP];
    __shared__ __align__(16) __nv_bfloat16 Bs[2][128][LDP];
    __shared__ float sbuf[32][132];                 // epilogue staging
    __shared__ int scx[128], scy[128], scb[128];    // col (distractor) coords
    __shared__ int srx[128], sry[128], srb[128];    // row (query) xy2/batch

    int t  = threadIdx.x;
    int q0 = blockIdx.y * 128;
    int d0 = blockIdx.x * 128;

    if (t < 128) {
        int d = min(d0 + t, ND - 1);
        int b3 = d / QB, rd = d % QB;
        scb[t] = b3;
        scy[t] = 16 + (rd / GW) * 8;
        scx[t] = 16 + (rd % GW) * 8;
        int q = min(q0 + t, Q_ - 1);
        int2 xy = g_xy2[q];
        srx[t] = xy.x; sry[t] = xy.y; srb[t] = q / QB;
    }

    int warp = t >> 5, lane = t & 31;
    int wm = warp & 3;        // 4 warps along M (32 rows each)
    int wn = warp >> 2;       // 2 warps along N (64 cols each)

    // per-thread staging addresses (two 16B segments for A and B each)
    int row0 = t >> 2,          seg0 = t & 3;
    int row1 = (t + 256) >> 2,  seg1 = (t + 256) & 3;
    const __nv_bfloat16* srcA0 = &g_a[(size_t)min(q0 + row0, Q_ - 1) * KSP + seg0 * 8];
    const __nv_bfloat16* srcB0 = &g_b[(size_t)min(d0 + row0, ND - 1) * KSP + seg0 * 8];
    const __nv_bfloat16* srcA1 = &g_a[(size_t)min(q0 + row1, Q_ - 1) * KSP + seg1 * 8];
    const __nv_bfloat16* srcB1 = &g_b[(size_t)min(d0 + row1, ND - 1) * KSP + seg1 * 8];

    float acc[2][8][4];
#pragma unroll
    for (int i = 0; i < 2; i++)
#pragma unroll
        for (int j = 0; j < 8; j++)
#pragma unroll
            for (int c = 0; c < 4; c++) acc[i][j][c] = 0.0f;

    uint4 ra0 = *(const uint4*)(srcA0);
    uint4 rb0 = *(const uint4*)(srcB0);
    uint4 ra1 = *(const uint4*)(srcA1);
    uint4 rb1 = *(const uint4*)(srcB1);

    for (int kc = 0; kc < KSP; kc += 32) {
        __syncthreads();            // previous chunk's compute finished
        *(uint4*)&As[seg0 >> 1][row0][(seg0 & 1) * 8] = ra0;
        *(uint4*)&Bs[seg0 >> 1][row0][(seg0 & 1) * 8] = rb0;
        *(uint4*)&As[seg1 >> 1][row1][(seg1 & 1) * 8] = ra1;
        *(uint4*)&Bs[seg1 >> 1][row1][(seg1 & 1) * 8] = rb1;
        __syncthreads();            // staging visible
        if (kc + 32 < KSP) {        // prefetch next chunk (overlaps MMA below)
            ra0 = *(const uint4*)(srcA0 + kc + 32);
            rb0 = *(const uint4*)(srcB0 + kc + 32);
            ra1 = *(const uint4*)(srcA1 + kc + 32);
            rb1 = *(const uint4*)(srcB1 + kc + 32);
        }
#pragma unroll
        for (int s = 0; s < 2; s++) {
            uint32_t af[2][4], bf[4][4];
            int rsel = lane & 15;
            int csel = (lane >> 4) * 8;
#pragma unroll
            for (int i = 0; i < 2; i++)
                ldsm_x4(af[i], &As[s][wm * 32 + i * 16 + rsel][csel]);
#pragma unroll
            for (int j4 = 0; j4 < 4; j4++)
                ldsm_x4(bf[j4], &Bs[s][wn * 64 + j4 * 16 + rsel][csel]);
#pragma unroll
            for (int i = 0; i < 2; i++)
#pragma unroll
                for (int j = 0; j < 8; j++)
                    mma_bf16(acc[i][j], af[i], bf[j >> 1][j & 1], bf[j >> 1][(j & 1) + 2]);
        }
    }
    __syncthreads();

    // epilogue: 4 chunks of 32 rows; stage via smem, emit lane-contiguous stores
    int group = lane >> 2, tig = lane & 3;
#pragma unroll 1
    for (int w = 0; w < 4; w++) {
        if (wm == w) {
#pragma unroll
            for (int i = 0; i < 2; i++)
#pragma unroll
                for (int j = 0; j < 8; j++)
#pragma unroll
                    for (int c = 0; c < 4; c++) {
                        int rl = i * 16 + group + (c >> 1) * 8;
                        int cl = wn * 64 + j * 8 + tig * 2 + (c & 1);
                        sbuf[rl][cl] = acc[i][j][c];
                    }
        }
        __syncthreads();
        // readout: each warp owns 4 rows; lanes contiguous over columns
#pragma unroll
        for (int r4 = 0; r4 < 4; r4++) {
            int rl = warp * 4 + r4;
            int q  = q0 + w * 32 + rl;
            if (q < Q_) {
                int qx = srx[w * 32 + rl], qy = sry[w * 32 + rl], qb = srb[w * 32 + rl];
                float* so = out + (size_t)q * NCOL + 1 + NNEG;
                float* go = out + S_SCORES + (size_t)q * NCOL + 1 + NNEG;
#pragma unroll
                for (int c4 = 0; c4 < 4; c4++) {
                    int col = c4 * 32 + lane;
                    int d = d0 + col;
                    if (d0 + c4 * 32 < ND) {       // chunk-uniform validity (32 | ND-d0)
                        int dx = scx[col] - qx, dy = scy[col] - qy;
                        int dis2 = dx * dx + dy * dy + (scb[col] != qb ? 25 : 0);
                        so[d] = (dis2 < 25) ? 0.0f : sbuf[rl][col];
                        go[d] = 0.0f;
                    }
                }
            }
        }
        __syncthreads();
    }
}

// ---------------- launch ----------------
extern "C" void kernel_launch(void* const* d_in, const int* in_sizes, int n_in,
                              void* d_out, int out_size) {
    const float* feat1 = (const float*)d_in[0];
    const float* feat2 = (const float*)d_in[1];
    const float* conf1 = (const float*)d_in[2];
    const float* conf2 = (const float*)d_in[3];
    const float* aflow = (const float*)d_in[4];
    float* out = (float*)d_out;
    (void)in_sizes; (void)n_in; (void)out_size;

    dim3 tb(32, 8);
    dim3 tg((H_ * W_) / 64, C_ / 32, B_);
    k_transpose<<<tg, tb>>>(feat2);

    k_posneg<<<Q_, 256>>>(feat1, conf1, conf2, aflow, out);

    dim3 gg(MPAD / 128, MPAD / 128);
    k_gemm<<<gg, 256>>>(out);
}

// round 13
// speedup vs baseline: 1.5630x; 1.0911x over previous
#include <cuda_runtime.h>
#include <cuda_fp16.h>
#include <cstdint>

#define B_    4
#define C_    128
#define H_    256
#define W_    256
#define GW    28
#define QB    784
#define Q_    3136
#define NPOS  29
#define NNEG  80
#define NOFF  109
#define ND    3136
#define NCOL  3217   /* 1 + 80 + 3136 */
#define MPAD  3200   /* 25 * 128 */
#define KSP   256    /* 2 * 128 : [hiA|loA] x [hiB|hiB]  (fp16 split) */

static const size_t S_SCORES = (size_t)Q_ * NCOL;   // 10,088,512

// ---------------- offsets, exact reference enumeration order (j outer asc, i inner asc)
__constant__ int c_off[NOFF][2] = {
    // ---- 29 positives ----
    {0,-3},
    {-2,-2},{-1,-2},{0,-2},{1,-2},{2,-2},
    {-2,-1},{-1,-1},{0,-1},{1,-1},{2,-1},
    {-3,0},{-2,0},{-1,0},{0,0},{1,0},{2,0},{3,0},
    {-2,1},{-1,1},{0,1},{1,1},{2,1},
    {-2,2},{-1,2},{0,2},{1,2},{2,2},
    {0,3},
    // ---- 80 negatives ----
    {0,-7},
    {-3,-6},{-2,-6},{-1,-6},{0,-6},{1,-6},{2,-6},{3,-6},
    {-4,-5},{-3,-5},{-2,-5},{-1,-5},{0,-5},{1,-5},{2,-5},{3,-5},{4,-5},
    {-5,-4},{-4,-4},{-3,-4},{3,-4},{4,-4},{5,-4},
    {-6,-3},{-5,-3},{-4,-3},{4,-3},{5,-3},{6,-3},
    {-6,-2},{-5,-2},{5,-2},{6,-2},
    {-6,-1},{-5,-1},{5,-1},{6,-1},
    {-7,0},{-6,0},{-5,0},{5,0},{6,0},{7,0},
    {-6,1},{-5,1},{5,1},{6,1},
    {-6,2},{-5,2},{5,2},{6,2},
    {-6,3},{-5,3},{-4,3},{4,3},{5,3},{6,3},
    {-5,4},{-4,4},{-3,4},{3,4},{4,4},{5,4},
    {-4,5},{-3,5},{-2,5},{-1,5},{0,5},{1,5},{2,5},{3,5},{4,5},
    {-3,6},{-2,6},{-1,6},{0,6},{1,6},{2,6},{3,6},
    {0,7}
};

// ---------------- device scratch ----------------
__device__ float g_feat2t[(size_t)B_ * H_ * W_ * C_];       // feat2 -> (B,H,W,C)
__device__ __half g_a[(size_t)MPAD * KSP];                  // split queries [hi|lo]
__device__ __half g_b[(size_t)MPAD * KSP];                  // distractors   [hi|hi]
__device__ int2  g_xy2[Q_];

// ---------------- helpers ----------------
__device__ __forceinline__ void ldsm_x4(uint32_t (&r)[4], const void* p) {
    uint32_t a = (uint32_t)__cvta_generic_to_shared(p);
    asm volatile("ldmatrix.sync.aligned.m8n8.x4.shared.b16 {%0,%1,%2,%3}, [%4];"
        : "=r"(r[0]), "=r"(r[1]), "=r"(r[2]), "=r"(r[3]) : "r"(a));
}
__device__ __forceinline__ void mma_f16(float (&d)[4], const uint32_t (&a)[4],
                                        uint32_t b0, uint32_t b1) {
    asm volatile("mma.sync.aligned.m16n8k16.row.col.f32.f16.f16.f32 "
        "{%0,%1,%2,%3}, {%4,%5,%6,%7}, {%8,%9}, {%0,%1,%2,%3};"
        : "+f"(d[0]), "+f"(d[1]), "+f"(d[2]), "+f"(d[3])
        : "r"(a[0]), "r"(a[1]), "r"(a[2]), "r"(a[3]), "r"(b0), "r"(b1));
}

// ---------------- transpose feat2 (B,C,H,W) -> (B,HW,C), 64-pixel tiles ----------------
__global__ void k_transpose(const float* __restrict__ f2) {
    __shared__ float tile[32][65];
    int b  = blockIdx.z;
    int p0 = blockIdx.x * 64;     // pixel (h*W+w)
    int c0 = blockIdx.y * 32;     // channel
    int tx = threadIdx.x, ty = threadIdx.y;     // 32 x 8
    const float* src = f2 + (size_t)b * C_ * H_ * W_;
    float* dst = g_feat2t + (size_t)b * H_ * W_ * C_;
#pragma unroll
    for (int i = 0; i < 32; i += 8) {
        tile[ty + i][tx]      = src[(size_t)(c0 + ty + i) * (H_ * W_) + p0 + tx];
        tile[ty + i][tx + 32] = src[(size_t)(c0 + ty + i) * (H_ * W_) + p0 + 32 + tx];
    }
    __syncthreads();
#pragma unroll
    for (int i = 0; i < 8; i++)
        dst[(size_t)(p0 + ty + 8 * i) * C_ + c0 + tx] = tile[tx][ty + 8 * i];
}

// ---------------- per-query: gathers + fp16 split production, pos/neg scores,
// mask/qconf/gt[0:81].  Offsets phase unchanged (passing since R7).
__global__ void __launch_bounds__(256) k_posneg(const float* __restrict__ feat1,
                                                const float* __restrict__ conf1,
                                                const float* __restrict__ conf2,
                                                const float* __restrict__ aflow,
                                                float* __restrict__ out) {
    int q   = blockIdx.x;
    int tid = threadIdx.x;
    int b = q / QB;
    int r = q % QB;
    int y = 16 + (r / GW) * 8;
    int x = 16 + (r % GW) * 8;

    __shared__ __align__(16) float f1s[C_];
    __shared__ float pos_s[NPOS];
    __shared__ int2  sxy;

    if (tid < C_) {
        // f1 gather (strided over channels) + fp16 hi/lo split
        float f1v = feat1[(((size_t)b * C_ + tid) * H_ + y) * W_ + x];
        f1s[tid] = f1v;
        __half hi = __float2half(f1v);
        __half lo = __float2half(f1v - __half2float(hi));
        __half* arow = g_a + (size_t)q * KSP;
        arow[tid] = hi; arow[128 + tid] = lo;
        // distractor feature gather (coalesced from transposed layout), hi duplicated
        float f2v = g_feat2t[(((size_t)b * H_ + y) * W_ + x) * C_ + tid];
        __half hi2 = __float2half(f2v);
        __half* brow = g_b + (size_t)q * KSP;
        brow[tid] = hi2; brow[128 + tid] = hi2;
    }
    if (tid >= 128 && tid < 128 + 81)
        out[S_SCORES + (size_t)q * NCOL + (tid - 128)] = (tid == 128) ? 1.0f : 0.0f;
    if (tid == 0) {
        float ax = aflow[(((size_t)b * 2 + 0) * H_ + y) * W_ + x];
        float ay = aflow[(((size_t)b * 2 + 1) * H_ + y) * W_ + x];
        int x2 = (int)(ax + 0.5f);
        int y2 = (int)(ay + 0.5f);
        sxy = make_int2(x2, y2);
        g_xy2[q] = sxy;
        bool m = (x2 >= 0) && (y2 >= 0) && (x2 < W_) && (y2 < H_);
        out[2 * S_SCORES + q] = m ? 1.0f : 0.0f;
    }
    __syncthreads();

    int2 xy2 = sxy;
    int lane = tid & 31, warp = tid >> 5;
    const float* f2b = g_feat2t + (size_t)b * H_ * W_ * C_;
    const float4* f1v4 = (const float4*)f1s;
    float4 a = f1v4[lane];

    #define GADDR(off) ((const float4*)(f2b + ((size_t)min(max(xy2.y + c_off[min((off), NOFF-1)][1], 0), H_ - 1) * W_ \
                         + min(max(xy2.x + c_off[min((off), NOFF-1)][0], 0), W_ - 1)) * C_) + lane)
    float4 v0 = *GADDR(2 * warp);
    float4 v1 = *GADDR(2 * warp + 1);
#pragma unroll
    for (int i = 0; i < 7; i++) {
        int o0 = 16 * i + 2 * warp;
        float4 n0, n1;
        if (i < 6) {
            n0 = *GADDR(o0 + 16);
            n1 = *GADDR(o0 + 17);
        }
        float s0 = v0.x * a.x + v0.y * a.y + v0.z * a.z + v0.w * a.w;
        float s1 = v1.x * a.x + v1.y * a.y + v1.z * a.z + v1.w * a.w;
        s0 += __shfl_xor_sync(0xffffffffu, s0, 16);
        s1 += __shfl_xor_sync(0xffffffffu, s1, 16);
        s0 += __shfl_xor_sync(0xffffffffu, s0, 8);
        s1 += __shfl_xor_sync(0xffffffffu, s1, 8);
        s0 += __shfl_xor_sync(0xffffffffu, s0, 4);
        s1 += __shfl_xor_sync(0xffffffffu, s1, 4);
        s0 += __shfl_xor_sync(0xffffffffu, s0, 2);
        s1 += __shfl_xor_sync(0xffffffffu, s1, 2);
        s0 += __shfl_xor_sync(0xffffffffu, s0, 1);
        s1 += __shfl_xor_sync(0xffffffffu, s1, 1);
        if (lane == 0) {
            if (o0 < NOFF) {
                if (o0 < NPOS) pos_s[o0] = s0;
                else out[(size_t)q * NCOL + 1 + (o0 - NPOS)] = s0;
            }
            if (o0 + 1 < NOFF) {
                if (o0 + 1 < NPOS) pos_s[o0 + 1] = s1;
                else out[(size_t)q * NCOL + 1 + (o0 + 1 - NPOS)] = s1;
            }
        }
        v0 = n0; v1 = n1;
    }
    #undef GADDR
    __syncthreads();

    if (tid == 0) {
        float best = pos_s[0];
        int bi = 0;
        for (int p = 1; p < NPOS; p++)
            if (pos_s[p] > best) { best = pos_s[p]; bi = p; }
        out[(size_t)q * NCOL] = best;
        int sx = min(max(xy2.x + c_off[bi][0], 0), W_ - 1);
        int sy = min(max(xy2.y + c_off[bi][1], 0), H_ - 1);
        float c1 = conf1[((size_t)b * H_ + y)  * W_ + x];
        float c2 = conf2[((size_t)b * H_ + sy) * W_ + sx];
        out[2 * S_SCORES + Q_ + q] = 0.5f * (c1 + c2);
    }
}

// ---------------- dscores GEMM: fp16 tensor cores, K=256 split, mask+gt fused
// As/Bs padded to 24 halves per row (48B) -> conflict-free LDSM.
#define LDP 24
__global__ void __launch_bounds__(256) k_gemm(float* __restrict__ out) {
    __shared__ __align__(16) __half As[2][128][LDP];
    __shared__ __align__(16) __half Bs[2][128][LDP];
    __shared__ float sbuf[32][132];                 // epilogue staging
    __shared__ int scx[128], scy[128], scb[128];    // col (distractor) coords
    __shared__ int srx[128], sry[128], srb[128];    // row (query) xy2/batch

    int t  = threadIdx.x;
    int q0 = blockIdx.y * 128;
    int d0 = blockIdx.x * 128;

    if (t < 128) {
        int d = min(d0 + t, ND - 1);
        int b3 = d / QB, rd = d % QB;
        scb[t] = b3;
        scy[t] = 16 + (rd / GW) * 8;
        scx[t] = 16 + (rd % GW) * 8;
        int q = min(q0 + t, Q_ - 1);
        int2 xy = g_xy2[q];
        srx[t] = xy.x; sry[t] = xy.y; srb[t] = q / QB;
    }

    int warp = t >> 5, lane = t & 31;
    int wm = warp & 3;        // 4 warps along M (32 rows each)
    int wn = warp >> 2;       // 2 warps along N (64 cols each)

    // per-thread staging addresses (two 16B segments for A and B each)
    int row0 = t >> 2,          seg0 = t & 3;
    int row1 = (t + 256) >> 2,  seg1 = (t + 256) & 3;
    const __half* srcA0 = &g_a[(size_t)min(q0 + row0, Q_ - 1) * KSP + seg0 * 8];
    const __half* srcB0 = &g_b[(size_t)min(d0 + row0, ND - 1) * KSP + seg0 * 8];
    const __half* srcA1 = &g_a[(size_t)min(q0 + row1, Q_ - 1) * KSP + seg1 * 8];
    const __half* srcB1 = &g_b[(size_t)min(d0 + row1, ND - 1) * KSP + seg1 * 8];

    float acc[2][8][4];
#pragma unroll
    for (int i = 0; i < 2; i++)
#pragma unroll
        for (int j = 0; j < 8; j++)
#pragma unroll
            for (int c = 0; c < 4; c++) acc[i][j][c] = 0.0f;

    uint4 ra0 = *(const uint4*)(srcA0);
    uint4 rb0 = *(const uint4*)(srcB0);
    uint4 ra1 = *(const uint4*)(srcA1);
    uint4 rb1 = *(const uint4*)(srcB1);

    for (int kc = 0; kc < KSP; kc += 32) {
        __syncthreads();            // previous chunk's compute finished
        *(uint4*)&As[seg0 >> 1][row0][(seg0 & 1) * 8] = ra0;
        *(uint4*)&Bs[seg0 >> 1][row0][(seg0 & 1) * 8] = rb0;
        *(uint4*)&As[seg1 >> 1][row1][(seg1 & 1) * 8] = ra1;
        *(uint4*)&Bs[seg1 >> 1][row1][(seg1 & 1) * 8] = rb1;
        __syncthreads();            // staging visible
        if (kc + 32 < KSP) {        // prefetch next chunk (overlaps MMA below)
            ra0 = *(const uint4*)(srcA0 + kc + 32);
            rb0 = *(const uint4*)(srcB0 + kc + 32);
            ra1 = *(const uint4*)(srcA1 + kc + 32);
            rb1 = *(const uint4*)(srcB1 + kc + 32);
        }
#pragma unroll
        for (int s = 0; s < 2; s++) {
            uint32_t af[2][4], bf[4][4];
            int rsel = lane & 15;
            int csel = (lane >> 4) * 8;
#pragma unroll
            for (int i = 0; i < 2; i++)
                ldsm_x4(af[i], &As[s][wm * 32 + i * 16 + rsel][csel]);
#pragma unroll
            for (int j4 = 0; j4 < 4; j4++)
                ldsm_x4(bf[j4], &Bs[s][wn * 64 + j4 * 16 + rsel][csel]);
#pragma unroll
            for (int i = 0; i < 2; i++)
#pragma unroll
                for (int j = 0; j < 8; j++)
                    mma_f16(acc[i][j], af[i], bf[j >> 1][j & 1], bf[j >> 1][(j & 1) + 2]);
        }
    }
    __syncthreads();

    // epilogue: 4 chunks of 32 rows; stage via smem, emit lane-contiguous stores
    int group = lane >> 2, tig = lane & 3;
#pragma unroll 1
    for (int w = 0; w < 4; w++) {
        if (wm == w) {
#pragma unroll
            for (int i = 0; i < 2; i++)
#pragma unroll
                for (int j = 0; j < 8; j++)
#pragma unroll
                    for (int c = 0; c < 4; c++) {
                        int rl = i * 16 + group + (c >> 1) * 8;
                        int cl = wn * 64 + j * 8 + tig * 2 + (c & 1);
                        sbuf[rl][cl] = acc[i][j][c];
                    }
        }
        __syncthreads();
        // readout: each warp owns 4 rows; lanes contiguous over columns
#pragma unroll
        for (int r4 = 0; r4 < 4; r4++) {
            int rl = warp * 4 + r4;
            int q  = q0 + w * 32 + rl;
            if (q < Q_) {
                int qx = srx[w * 32 + rl], qy = sry[w * 32 + rl], qb = srb[w * 32 + rl];
                float* so = out + (size_t)q * NCOL + 1 + NNEG;
                float* go = out + S_SCORES + (size_t)q * NCOL + 1 + NNEG;
#pragma unroll
                for (int c4 = 0; c4 < 4; c4++) {
                    int col = c4 * 32 + lane;
                    int d = d0 + col;
                    if (d0 + c4 * 32 < ND) {       // chunk-uniform validity (32 | ND-d0)
                        int dx = scx[col] - qx, dy = scy[col] - qy;
                        int dis2 = dx * dx + dy * dy + (scb[col] != qb ? 25 : 0);
                        so[d] = (dis2 < 25) ? 0.0f : sbuf[rl][col];
                        go[d] = 0.0f;
                    }
                }
            }
        }
        __syncthreads();
    }
}

// ---------------- launch ----------------
extern "C" void kernel_launch(void* const* d_in, const int* in_sizes, int n_in,
                              void* d_out, int out_size) {
    const float* feat1 = (const float*)d_in[0];
    const float* feat2 = (const float*)d_in[1];
    const float* conf1 = (const float*)d_in[2];
    const float* conf2 = (const float*)d_in[3];
    const float* aflow = (const float*)d_in[4];
    float* out = (float*)d_out;
    (void)in_sizes; (void)n_in; (void)out_size;

    dim3 tb(32, 8);
    dim3 tg((H_ * W_) / 64, C_ / 32, B_);
    k_transpose<<<tg, tb>>>(feat2);

    k_posneg<<<Q_, 256>>>(feat1, conf1, conf2, aflow, out);

    dim3 gg(MPAD / 128, MPAD / 128);
    k_gemm<<<gg, 256>>>(out);
}

// round 14
// speedup vs baseline: 1.7700x; 1.1324x over previous
#include <cuda_runtime.h>
#include <cuda_fp16.h>
#include <cstdint>

#define B_    4
#define C_    128
#define H_    256
#define W_    256
#define GW    28
#define QB    784
#define Q_    3136
#define NPOS  29
#define NNEG  80
#define NOFF  109
#define ND    3136
#define NCOL  3217   /* 1 + 80 + 3136 */
#define MPAD  3200   /* 25 * 128 */
#define KSP   256    /* 2 * 128 : [hiA|loA] x [hiB|hiB]  (fp16 split) */

static const size_t S_SCORES = (size_t)Q_ * NCOL;   // 10,088,512

// ---------------- offsets, exact reference enumeration order (j outer asc, i inner asc)
__constant__ int c_off[NOFF][2] = {
    // ---- 29 positives ----
    {0,-3},
    {-2,-2},{-1,-2},{0,-2},{1,-2},{2,-2},
    {-2,-1},{-1,-1},{0,-1},{1,-1},{2,-1},
    {-3,0},{-2,0},{-1,0},{0,0},{1,0},{2,0},{3,0},
    {-2,1},{-1,1},{0,1},{1,1},{2,1},
    {-2,2},{-1,2},{0,2},{1,2},{2,2},
    {0,3},
    // ---- 80 negatives ----
    {0,-7},
    {-3,-6},{-2,-6},{-1,-6},{0,-6},{1,-6},{2,-6},{3,-6},
    {-4,-5},{-3,-5},{-2,-5},{-1,-5},{0,-5},{1,-5},{2,-5},{3,-5},{4,-5},
    {-5,-4},{-4,-4},{-3,-4},{3,-4},{4,-4},{5,-4},
    {-6,-3},{-5,-3},{-4,-3},{4,-3},{5,-3},{6,-3},
    {-6,-2},{-5,-2},{5,-2},{6,-2},
    {-6,-1},{-5,-1},{5,-1},{6,-1},
    {-7,0},{-6,0},{-5,0},{5,0},{6,0},{7,0},
    {-6,1},{-5,1},{5,1},{6,1},
    {-6,2},{-5,2},{5,2},{6,2},
    {-6,3},{-5,3},{-4,3},{4,3},{5,3},{6,3},
    {-5,4},{-4,4},{-3,4},{3,4},{4,4},{5,4},
    {-4,5},{-3,5},{-2,5},{-1,5},{0,5},{1,5},{2,5},{3,5},{4,5},
    {-3,6},{-2,6},{-1,6},{0,6},{1,6},{2,6},{3,6},
    {0,7}
};

// ---------------- device scratch ----------------
__device__ __half g_feat2t[(size_t)B_ * H_ * W_ * C_];      // feat2 -> (B,H,W,C), fp16
__device__ __half g_a[(size_t)MPAD * KSP];                  // split queries [hi|lo]
__device__ __half g_b[(size_t)MPAD * KSP];                  // distractors   [hi|hi]
__device__ int2  g_xy2[Q_];

// ---------------- helpers ----------------
__device__ __forceinline__ void ldsm_x4(uint32_t (&r)[4], const void* p) {
    uint32_t a = (uint32_t)__cvta_generic_to_shared(p);
    asm volatile("ldmatrix.sync.aligned.m8n8.x4.shared.b16 {%0,%1,%2,%3}, [%4];"
        : "=r"(r[0]), "=r"(r[1]), "=r"(r[2]), "=r"(r[3]) : "r"(a));
}
__device__ __forceinline__ void mma_f16(float (&d)[4], const uint32_t (&a)[4],
                                        uint32_t b0, uint32_t b1) {
    asm volatile("mma.sync.aligned.m16n8k16.row.col.f32.f16.f16.f32 "
        "{%0,%1,%2,%3}, {%4,%5,%6,%7}, {%8,%9}, {%0,%1,%2,%3};"
        : "+f"(d[0]), "+f"(d[1]), "+f"(d[2]), "+f"(d[3])
        : "r"(a[0]), "r"(a[1]), "r"(a[2]), "r"(a[3]), "r"(b0), "r"(b1));
}

// ---------------- transpose feat2 (B,C,H,W) fp32 -> (B,HW,C) fp16, 64-pixel tiles
__global__ void k_transpose(const float* __restrict__ f2) {
    __shared__ float tile[32][65];
    int b  = blockIdx.z;
    int p0 = blockIdx.x * 64;     // pixel (h*W+w)
    int c0 = blockIdx.y * 32;     // channel
    int tx = threadIdx.x, ty = threadIdx.y;     // 32 x 8
    const float* src = f2 + (size_t)b * C_ * H_ * W_;
    __half* dst = g_feat2t + (size_t)b * H_ * W_ * C_;
#pragma unroll
    for (int i = 0; i < 32; i += 8) {
        tile[ty + i][tx]      = src[(size_t)(c0 + ty + i) * (H_ * W_) + p0 + tx];
        tile[ty + i][tx + 32] = src[(size_t)(c0 + ty + i) * (H_ * W_) + p0 + 32 + tx];
    }
    __syncthreads();
#pragma unroll
    for (int i = 0; i < 8; i++)
        dst[(size_t)(p0 + ty + 8 * i) * C_ + c0 + tx] = __float2half(tile[tx][ty + 8 * i]);
}

// ---------------- per-query: gathers + fp16 split production, pos/neg scores,
// mask/qconf/gt[0:81].  Patch dots read fp16 feat2t, accumulate fp32.
__global__ void __launch_bounds__(256) k_posneg(const float* __restrict__ feat1,
                                                const float* __restrict__ conf1,
                                                const float* __restrict__ conf2,
                                                const float* __restrict__ aflow,
                                                float* __restrict__ out) {
    int q   = blockIdx.x;
    int tid = threadIdx.x;
    int b = q / QB;
    int r = q % QB;
    int y = 16 + (r / GW) * 8;
    int x = 16 + (r % GW) * 8;

    __shared__ __align__(16) float f1s[C_];
    __shared__ float pos_s[NPOS];
    __shared__ int2  sxy;

    if (tid < C_) {
        // f1 gather (strided over channels) + fp16 hi/lo split
        float f1v = feat1[(((size_t)b * C_ + tid) * H_ + y) * W_ + x];
        f1s[tid] = f1v;
        __half hi = __float2half(f1v);
        __half lo = __float2half(f1v - __half2float(hi));
        __half* arow = g_a + (size_t)q * KSP;
        arow[tid] = hi; arow[128 + tid] = lo;
        // distractor feature gather: feat2t already fp16 == fp16(feat2) — bit-identical B operand
        __half hv = g_feat2t[(((size_t)b * H_ + y) * W_ + x) * C_ + tid];
        __half* brow = g_b + (size_t)q * KSP;
        brow[tid] = hv; brow[128 + tid] = hv;
    }
    if (tid >= 128 && tid < 128 + 81)
        out[S_SCORES + (size_t)q * NCOL + (tid - 128)] = (tid == 128) ? 1.0f : 0.0f;
    if (tid == 0) {
        float ax = aflow[(((size_t)b * 2 + 0) * H_ + y) * W_ + x];
        float ay = aflow[(((size_t)b * 2 + 1) * H_ + y) * W_ + x];
        int x2 = (int)(ax + 0.5f);
        int y2 = (int)(ay + 0.5f);
        sxy = make_int2(x2, y2);
        g_xy2[q] = sxy;
        bool m = (x2 >= 0) && (y2 >= 0) && (x2 < W_) && (y2 < H_);
        out[2 * S_SCORES + q] = m ? 1.0f : 0.0f;
    }
    __syncthreads();

    int2 xy2 = sxy;
    int lane = tid & 31, warp = tid >> 5;
    const __half* f2b = g_feat2t + (size_t)b * H_ * W_ * C_;
    const float4* f1v4 = (const float4*)f1s;
    float4 a = f1v4[lane];          // lane owns channels 4*lane..4*lane+3

    // lane reads 4 halves (8B) per patch pixel
    #define GADDR(off) ((const uint2*)(f2b + ((size_t)min(max(xy2.y + c_off[min((off), NOFF-1)][1], 0), H_ - 1) * W_ \
                         + min(max(xy2.x + c_off[min((off), NOFF-1)][0], 0), W_ - 1)) * C_) + lane)
    uint2 v0 = *GADDR(2 * warp);
    uint2 v1 = *GADDR(2 * warp + 1);
#pragma unroll
    for (int i = 0; i < 7; i++) {
        int o0 = 16 * i + 2 * warp;
        uint2 n0, n1;
        if (i < 6) {
            n0 = *GADDR(o0 + 16);
            n1 = *GADDR(o0 + 17);
        }
        const __half2* h0 = (const __half2*)&v0;
        const __half2* h1 = (const __half2*)&v1;
        float2 p00 = __half22float2(h0[0]), p01 = __half22float2(h0[1]);
        float2 p10 = __half22float2(h1[0]), p11 = __half22float2(h1[1]);
        float s0 = p00.x * a.x + p00.y * a.y + p01.x * a.z + p01.y * a.w;
        float s1 = p10.x * a.x + p10.y * a.y + p11.x * a.z + p11.y * a.w;
        s0 += __shfl_xor_sync(0xffffffffu, s0, 16);
        s1 += __shfl_xor_sync(0xffffffffu, s1, 16);
        s0 += __shfl_xor_sync(0xffffffffu, s0, 8);
        s1 += __shfl_xor_sync(0xffffffffu, s1, 8);
        s0 += __shfl_xor_sync(0xffffffffu, s0, 4);
        s1 += __shfl_xor_sync(0xffffffffu, s1, 4);
        s0 += __shfl_xor_sync(0xffffffffu, s0, 2);
        s1 += __shfl_xor_sync(0xffffffffu, s1, 2);
        s0 += __shfl_xor_sync(0xffffffffu, s0, 1);
        s1 += __shfl_xor_sync(0xffffffffu, s1, 1);
        if (lane == 0) {
            if (o0 < NOFF) {
                if (o0 < NPOS) pos_s[o0] = s0;
                else out[(size_t)q * NCOL + 1 + (o0 - NPOS)] = s0;
            }
            if (o0 + 1 < NOFF) {
                if (o0 + 1 < NPOS) pos_s[o0 + 1] = s1;
                else out[(size_t)q * NCOL + 1 + (o0 + 1 - NPOS)] = s1;
            }
        }
        v0 = n0; v1 = n1;
    }
    #undef GADDR
    __syncthreads();

    if (tid == 0) {
        float best = pos_s[0];
        int bi = 0;
        for (int p = 1; p < NPOS; p++)
            if (pos_s[p] > best) { best = pos_s[p]; bi = p; }
        out[(size_t)q * NCOL] = best;
        int sx = min(max(xy2.x + c_off[bi][0], 0), W_ - 1);
        int sy = min(max(xy2.y + c_off[bi][1], 0), H_ - 1);
        float c1 = conf1[((size_t)b * H_ + y)  * W_ + x];
        float c2 = conf2[((size_t)b * H_ + sy) * W_ + sx];
        out[2 * S_SCORES + Q_ + q] = 0.5f * (c1 + c2);
    }
}

// ---------------- dscores GEMM: fp16 tensor cores, K=256 split, mask+gt fused
// As/Bs padded to 24 halves per row (48B) -> conflict-free LDSM. (unchanged from R13)
#define LDP 24
__global__ void __launch_bounds__(256) k_gemm(float* __restrict__ out) {
    __shared__ __align__(16) __half As[2][128][LDP];
    __shared__ __align__(16) __half Bs[2][128][LDP];
    __shared__ float sbuf[32][132];                 // epilogue staging
    __shared__ int scx[128], scy[128], scb[128];    // col (distractor) coords
    __shared__ int srx[128], sry[128], srb[128];    // row (query) xy2/batch

    int t  = threadIdx.x;
    int q0 = blockIdx.y * 128;
    int d0 = blockIdx.x * 128;

    if (t < 128) {
        int d = min(d0 + t, ND - 1);
        int b3 = d / QB, rd = d % QB;
        scb[t] = b3;
        scy[t] = 16 + (rd / GW) * 8;
        scx[t] = 16 + (rd % GW) * 8;
        int q = min(q0 + t, Q_ - 1);
        int2 xy = g_xy2[q];
        srx[t] = xy.x; sry[t] = xy.y; srb[t] = q / QB;
    }

    int warp = t >> 5, lane = t & 31;
    int wm = warp & 3;        // 4 warps along M (32 rows each)
    int wn = warp >> 2;       // 2 warps along N (64 cols each)

    // per-thread staging addresses (two 16B segments for A and B each)
    int row0 = t >> 2,          seg0 = t & 3;
    int row1 = (t + 256) >> 2,  seg1 = (t + 256) & 3;
    const __half* srcA0 = &g_a[(size_t)min(q0 + row0, Q_ - 1) * KSP + seg0 * 8];
    const __half* srcB0 = &g_b[(size_t)min(d0 + row0, ND - 1) * KSP + seg0 * 8];
    const __half* srcA1 = &g_a[(size_t)min(q0 + row1, Q_ - 1) * KSP + seg1 * 8];
    const __half* srcB1 = &g_b[(size_t)min(d0 + row1, ND - 1) * KSP + seg1 * 8];

    float acc[2][8][4];
#pragma unroll
    for (int i = 0; i < 2; i++)
#pragma unroll
        for (int j = 0; j < 8; j++)
#pragma unroll
            for (int c = 0; c < 4; c++) acc[i][j][c] = 0.0f;

    uint4 ra0 = *(const uint4*)(srcA0);
    uint4 rb0 = *(const uint4*)(srcB0);
    uint4 ra1 = *(const uint4*)(srcA1);
    uint4 rb1 = *(const uint4*)(srcB1);

    for (int kc = 0; kc < KSP; kc += 32) {
        __syncthreads();            // previous chunk's compute finished
        *(uint4*)&As[seg0 >> 1][row0][(seg0 & 1) * 8] = ra0;
        *(uint4*)&Bs[seg0 >> 1][row0][(seg0 & 1) * 8] = rb0;
        *(uint4*)&As[seg1 >> 1][row1][(seg1 & 1) * 8] = ra1;
        *(uint4*)&Bs[seg1 >> 1][row1][(seg1 & 1) * 8] = rb1;
        __syncthreads();            // staging visible
        if (kc + 32 < KSP) {        // prefetch next chunk (overlaps MMA below)
            ra0 = *(const uint4*)(srcA0 + kc + 32);
            rb0 = *(const uint4*)(srcB0 + kc + 32);
            ra1 = *(const uint4*)(srcA1 + kc + 32);
            rb1 = *(const uint4*)(srcB1 + kc + 32);
        }
#pragma unroll
        for (int s = 0; s < 2; s++) {
            uint32_t af[2][4], bf[4][4];
            int rsel = lane & 15;
            int csel = (lane >> 4) * 8;
#pragma unroll
            for (int i = 0; i < 2; i++)
                ldsm_x4(af[i], &As[s][wm * 32 + i * 16 + rsel][csel]);
#pragma unroll
            for (int j4 = 0; j4 < 4; j4++)
                ldsm_x4(bf[j4], &Bs[s][wn * 64 + j4 * 16 + rsel][csel]);
#pragma unroll
            for (int i = 0; i < 2; i++)
#pragma unroll
                for (int j = 0; j < 8; j++)
                    mma_f16(acc[i][j], af[i], bf[j >> 1][j & 1], bf[j >> 1][(j & 1) + 2]);
        }
    }
    __syncthreads();

    // epilogue: 4 chunks of 32 rows; stage via smem, emit lane-contiguous stores
    int group = lane >> 2, tig = lane & 3;
#pragma unroll 1
    for (int w = 0; w < 4; w++) {
        if (wm == w) {
#pragma unroll
            for (int i = 0; i < 2; i++)
#pragma unroll
                for (int j = 0; j < 8; j++)
#pragma unroll
                    for (int c = 0; c < 4; c++) {
                        int rl = i * 16 + group + (c >> 1) * 8;
                        int cl = wn * 64 + j * 8 + tig * 2 + (c & 1);
                        sbuf[rl][cl] = acc[i][j][c];
                    }
        }
        __syncthreads();
        // readout: each warp owns 4 rows; lanes contiguous over columns
#pragma unroll
        for (int r4 = 0; r4 < 4; r4++) {
            int rl = warp * 4 + r4;
            int q  = q0 + w * 32 + rl;
            if (q < Q_) {
                int qx = srx[w * 32 + rl], qy = sry[w * 32 + rl], qb = srb[w * 32 + rl];
                float* so = out + (size_t)q * NCOL + 1 + NNEG;
                float* go = out + S_SCORES + (size_t)q * NCOL + 1 + NNEG;
#pragma unroll
                for (int c4 = 0; c4 < 4; c4++) {
                    int col = c4 * 32 + lane;
                    int d = d0 + col;
                    if (d0 + c4 * 32 < ND) {       // chunk-uniform validity (32 | ND-d0)
                        int dx = scx[col] - qx, dy = scy[col] - qy;
                        int dis2 = dx * dx + dy * dy + (scb[col] != qb ? 25 : 0);
                        so[d] = (dis2 < 25) ? 0.0f : sbuf[rl][col];
                        go[d] = 0.0f;
                    }
                }
            }
        }
        __syncthreads();
    }
}

// ---------------- launch ----------------
extern "C" void kernel_launch(void* const* d_in, const int* in_sizes, int n_in,
                              void* d_out, int out_size) {
    const float* feat1 = (const float*)d_in[0];
    const float* feat2 = (const float*)d_in[1];
    const float* conf1 = (const float*)d_in[2];
    const float* conf2 = (const float*)d_in[3];
    const float* aflow = (const float*)d_in[4];
    float* out = (float*)d_out;
    (void)in_sizes; (void)n_in; (void)out_size;

    dim3 tb(32, 8);
    dim3 tg((H_ * W_) / 64, C_ / 32, B_);
    k_transpose<<<tg, tb>>>(feat2);

    k_posneg<<<Q_, 256>>>(feat1, conf1, conf2, aflow, out);

    dim3 gg(MPAD / 128, MPAD / 128);
    k_gemm<<<gg, 256>>>(out);
}